// round 1
// baseline (speedup 1.0000x reference)
#include <cuda_runtime.h>

// LIF neuron scan: T=8 timesteps, leaky integrate + threshold + reset-by-subtraction.
// x: [T*B, C, H, W] fp32 contiguous = [T, N] with N = B*C*H*W = 4,194,304.
// out[t, n] = spike(t, n) / DELTA_T.
// Pure streaming: 134 MB in, 134 MB out -> HBM-bound. One thread per float4 of
// neurons; the T=8 loop is fully unrolled so the 8 independent LDG.128 batch up
// front (MLP=8) while the mem-recurrence FMA chain overlaps.

#define T_STEPS 8
#define N_ELEM  (32 * 128 * 32 * 32)   // B*C*H*W per timestep
#define N4      (N_ELEM / 4)

__global__ __launch_bounds__(256) void lif_kernel(
    const float4* __restrict__ x,
    const float*  __restrict__ vth_ptr,
    float4*       __restrict__ out)
{
    int idx = blockIdx.x * blockDim.x + threadIdx.x;
    if (idx >= N4) return;

    // no-grad clamp: relu(Vth - bound) + bound
    float Vth = vth_ptr[0];
    Vth = fmaxf(Vth - 0.0005f, 0.0f) + 0.0005f;

    // beta = expf(-DELTA_T/TAU) = exp(-0.05f), correctly rounded fp32
    const float beta  = 0.9512294531f;      // fp32 nearest to exp(-0.05)
    const float omb   = 1.0f - beta;        // (1 - beta)
    const float thr   = 0.3f * Vth;         // ALPHA * Vth
    const float sval  = Vth * 20.0f;        // Vth / DELTA_T (output spike value)

    float mx = 0.f, my = 0.f, mz = 0.f, mw = 0.f;

#pragma unroll
    for (int t = 0; t < T_STEPS; t++) {
        float4 xt = x[(size_t)t * N4 + idx];

        mx = beta * mx + omb * xt.x;
        my = beta * my + omb * xt.y;
        mz = beta * mz + omb * xt.z;
        mw = beta * mw + omb * xt.w;

        float4 o;
        if (mx >= thr) { o.x = sval; mx -= Vth; } else { o.x = 0.f; }
        if (my >= thr) { o.y = sval; my -= Vth; } else { o.y = 0.f; }
        if (mz >= thr) { o.z = sval; mz -= Vth; } else { o.z = 0.f; }
        if (mw >= thr) { o.w = sval; mw -= Vth; } else { o.w = 0.f; }

        out[(size_t)t * N4 + idx] = o;
    }
}

extern "C" void kernel_launch(void* const* d_in, const int* in_sizes, int n_in,
                              void* d_out, int out_size) {
    const float4* x   = (const float4*)d_in[0];
    const float*  vth = (const float*)d_in[1];
    float4*       out = (float4*)d_out;

    dim3 block(256);
    dim3 grid(N4 / 256);   // 1,048,576 / 256 = 4096 blocks
    lif_kernel<<<grid, block>>>(x, vth, out);
}

// round 2
// speedup vs baseline: 1.0309x; 1.0309x over previous
#include <cuda_runtime.h>

// LIF neuron scan: T=8, leaky integrate + threshold + reset-by-subtraction.
// x: [T, N] fp32, N = 32*128*32*32 = 4,194,304. Pure streaming, HBM-bound.
//
// R2 change vs R1: explicitly batch all 8 LDG.128 into a front load phase
// (local float4 array) so MLP_p1 = 8 per thread, then compute + store.
// R1's interleaved loop left MLP ~1-2 (regs=32 proved no batching) and only
// reached 74% of HBM. Streaming hints (__ldcs/__stcs) since data has no reuse.

#define T_STEPS 8
#define N_ELEM  (32 * 128 * 32 * 32)
#define N4      (N_ELEM / 4)

__global__ __launch_bounds__(256) void lif_kernel(
    const float4* __restrict__ x,
    const float*  __restrict__ vth_ptr,
    float4*       __restrict__ out)
{
    int idx = blockIdx.x * blockDim.x + threadIdx.x;

    // ---- Phase 1: batch all 8 independent LDG.128 (MLP = 8) ----
    float4 xs[T_STEPS];
#pragma unroll
    for (int t = 0; t < T_STEPS; t++) {
        xs[t] = __ldcs(&x[(size_t)t * N4 + idx]);
    }

    // no-grad clamp: relu(Vth - bound) + bound
    float Vth = vth_ptr[0];
    Vth = fmaxf(Vth - 0.0005f, 0.0f) + 0.0005f;

    const float beta = 0.9512294531f;   // fp32 nearest to exp(-0.05)
    const float omb  = 1.0f - beta;
    const float thr  = 0.3f * Vth;
    const float sval = Vth * 20.0f;     // Vth / DELTA_T

    float mx = 0.f, my = 0.f, mz = 0.f, mw = 0.f;

    // ---- Phase 2: scan + streaming stores ----
#pragma unroll
    for (int t = 0; t < T_STEPS; t++) {
        float4 xt = xs[t];

        mx = beta * mx + omb * xt.x;
        my = beta * my + omb * xt.y;
        mz = beta * mz + omb * xt.z;
        mw = beta * mw + omb * xt.w;

        float4 o;
        if (mx >= thr) { o.x = sval; mx -= Vth; } else { o.x = 0.f; }
        if (my >= thr) { o.y = sval; my -= Vth; } else { o.y = 0.f; }
        if (mz >= thr) { o.z = sval; mz -= Vth; } else { o.z = 0.f; }
        if (mw >= thr) { o.w = sval; mw -= Vth; } else { o.w = 0.f; }

        __stcs(&out[(size_t)t * N4 + idx], o);
    }
}

extern "C" void kernel_launch(void* const* d_in, const int* in_sizes, int n_in,
                              void* d_out, int out_size) {
    const float4* x   = (const float4*)d_in[0];
    const float*  vth = (const float*)d_in[1];
    float4*       out = (float4*)d_out;

    lif_kernel<<<N4 / 256, 256>>>(x, vth, out);
}